// round 15
// baseline (speedup 1.0000x reference)
#include <cuda_runtime.h>
#include <stdint.h>

#define BB   4
#define NQ   2048
#define NP_  8192
#define DD   256
#define FF   40
#define KK   16
#define FULL 0xFFFFFFFFu

__device__ unsigned long long g_qcode[BB * NQ];
__device__ unsigned long long g_pcode[BB * NP_];

// ---- packed f32x2 helpers (Blackwell) --------------------------------------
__device__ __forceinline__ unsigned long long fmul2(
    unsigned long long a, unsigned long long b) {
    unsigned long long d;
    asm("mul.rn.f32x2 %0, %1, %2;" : "=l"(d) : "l"(a), "l"(b));
    return d;
}
__device__ __forceinline__ unsigned long long ffma2(
    unsigned long long a, unsigned long long b, unsigned long long c) {
    unsigned long long d;
    asm("fma.rn.f32x2 %0, %1, %2, %3;" : "=l"(d) : "l"(a), "l"(b), "l"(c));
    return d;
}
__device__ __forceinline__ float hsum2(unsigned long long v) {
    float lo, hi;
    asm("mov.b64 {%0, %1}, %2;" : "=f"(lo), "=f"(hi) : "l"(v));
    return lo + hi;
}

// ---------------------------------------------------------------------------
// Hash kernel: one warp per 4 rows; proj smem traffic amortized 4x; packed
// FFMA2 dot products with data loaded directly as ulonglong2 (no pack movs);
// 8-feature multi-reduction + ballot sign extraction (verified ordering).
// ---------------------------------------------------------------------------
__global__ __launch_bounds__(256) void hash_kernel(
    const float* __restrict__ qpts,
    const float* __restrict__ ppts,
    const float* __restrict__ proj,
    unsigned long long* __restrict__ qcodes,
    unsigned long long* __restrict__ pcodes)
{
    __shared__ __align__(16) float sproj[FF * DD];  // 40 KB
    {
        const float4* p4 = reinterpret_cast<const float4*>(proj);
        float4* s4 = reinterpret_cast<float4*>(sproj);
        for (int i = threadIdx.x; i < (FF * DD) / 4; i += blockDim.x)
            s4[i] = p4[i];
    }
    __syncthreads();

    const int warp = threadIdx.x >> 5;
    const int lane = threadIdx.x & 31;
    const int row0 = (blockIdx.x * 8 + warp) * 4;   // 1280*8*4 = 40960 exact

    const int NQT = BB * NQ;
    const float* src;
    unsigned long long* dst;
    int r0;
    if (row0 < NQT) { src = qpts; dst = qcodes; r0 = row0; }
    else            { src = ppts; dst = pcodes; r0 = row0 - NQT; }

    unsigned long long vp[4][4];
#pragma unroll
    for (int r = 0; r < 4; ++r) {
        const ulonglong2* rp = reinterpret_cast<const ulonglong2*>(
            src + (size_t)(r0 + r) * DD);
        ulonglong2 a = __ldg(rp + lane);        // floats 4L..4L+3 as 2 pairs
        ulonglong2 b = __ldg(rp + lane + 32);
        vp[r][0] = a.x; vp[r][1] = a.y; vp[r][2] = b.x; vp[r][3] = b.y;
    }

    const bool hi16 = (lane & 16) != 0;
    const bool hi8  = (lane & 8)  != 0;
    const bool hi4  = (lane & 4)  != 0;

    unsigned long long code[4] = {0ull, 0ull, 0ull, 0ull};

#pragma unroll
    for (int g = 0; g < 5; ++g) {
        const int brev[8] = {0, 4, 2, 6, 1, 5, 3, 7};
        float t[4][8];
#pragma unroll
        for (int s = 0; s < 8; ++s) {
            const int f = g * 8 + brev[s];
            const ulonglong2* sp = reinterpret_cast<const ulonglong2*>(sproj + f * DD);
            ulonglong2 P0 = sp[lane];
            ulonglong2 P1 = sp[lane + 32];
#pragma unroll
            for (int r = 0; r < 4; ++r) {
                unsigned long long acc = fmul2(vp[r][0], P0.x);
                acc = ffma2(vp[r][1], P0.y, acc);
                acc = ffma2(vp[r][2], P1.x, acc);
                acc = ffma2(vp[r][3], P1.y, acc);
                t[r][s] = hsum2(acc);
            }
        }
#pragma unroll
        for (int r = 0; r < 4; ++r) {
            float rr[4];
#pragma unroll
            for (int p = 0; p < 4; ++p) {
                float c = hi16 ? t[r][2 * p + 1] : t[r][2 * p];
                float d = hi16 ? t[r][2 * p]     : t[r][2 * p + 1];
                rr[p] = c + __shfl_xor_sync(FULL, d, 16);
            }
            float ss[2];
#pragma unroll
            for (int p = 0; p < 2; ++p) {
                float c = hi8 ? rr[2 * p + 1] : rr[2 * p];
                float d = hi8 ? rr[2 * p]     : rr[2 * p + 1];
                ss[p] = c + __shfl_xor_sync(FULL, d, 8);
            }
            float c = hi4 ? ss[1] : ss[0];
            float d = hi4 ? ss[0] : ss[1];
            float u = c + __shfl_xor_sync(FULL, d, 4);
            u += __shfl_xor_sync(FULL, u, 2);
            u += __shfl_xor_sync(FULL, u, 1);

            unsigned bal = __ballot_sync(FULL, u > 0.0f);
            unsigned x = bal & 0x11111111u;
            x = (x | (x >> 3))  & 0x03030303u;
            x = (x | (x >> 6))  & 0x000F000Fu;
            x = (x | (x >> 12)) & 0xFFu;
            code[r] |= (unsigned long long)x << (g * 8);
        }
    }
    if (lane == 0) {
        dst[r0 + 0] = code[0];
        dst[r0 + 1] = code[1];
        dst[r0 + 2] = code[2];
        dst[r0 + 3] = code[3];
    }
}

// ---------------------------------------------------------------------------
// knn kernel v4: one warp per query.
// Phase 1: fully unrolled branchless scan. Candidate keys are built RELATIVE
//   to the round: key_rel = dist*8192 + (2*lane + slotoff) with the 8 per-lane
//   addends hoisted into registers; the round base (g*1024 + r*256, an
//   immediate, < 8192) is added to the round minimum before the cross-round
//   MIN, giving exactly the same full key = dist*8192 + idx as before.
//   One try_insert per group of that group's 32 lane-minima.
// Phase 2: exact rescan of groups with gmin <= thr (same proof as R13/R14:
//   unique keys; a group with gmin > thr cannot hold a top-16 key; the group
//   min itself is provably resident in lst, deduped by masking to FULL).
// ---------------------------------------------------------------------------
__global__ __launch_bounds__(256, 4) void knn_kernel(float* __restrict__ out)
{
    const int gwarp = (blockIdx.x * blockDim.x + threadIdx.x) >> 5;
    const int lane  = threadIdx.x & 31;
    const int b     = gwarp >> 11;

    const unsigned long long qc = g_qcode[gwarp];
    const unsigned long long* __restrict__ pc = g_pcode + (size_t)b * NP_;
    const ulonglong2* __restrict__ pc2 = reinterpret_cast<const ulonglong2*>(pc);

    unsigned lst = FULL;   // lanes >= 16 keep FULL forever
    unsigned thr = FULL;

    auto try_insert = [&](unsigned key) {
        unsigned mask = __ballot_sync(FULL, key < thr);
        while (mask) {
            const int src = __ffs(mask) - 1;
            mask &= mask - 1;
            const unsigned kb  = __shfl_sync(FULL, key, src);
            const unsigned blt = __ballot_sync(FULL, lst < kb);
            const int pos = __popc(blt);
            if (pos < KK) {
                const unsigned up = __shfl_up_sync(FULL, lst, 1);
                if (lane < KK) {
                    if (lane > pos)       lst = up;
                    else if (lane == pos) lst = kb;
                }
                thr = __shfl_sync(FULL, lst, KK - 1);
                mask &= __ballot_sync(FULL, key < thr);
            }
        }
    };

    // Hoisted per-lane relative index addends (slot order fixed per round)
    const unsigned L2 = (unsigned)lane * 2u;
    const unsigned e0 = L2,       e1 = L2 + 1;
    const unsigned e2 = L2 + 64,  e3 = L2 + 65;
    const unsigned e4 = L2 + 128, e5 = L2 + 129;
    const unsigned e6 = L2 + 192, e7 = L2 + 193;

    unsigned gm[8];
#pragma unroll
    for (int g = 0; g < 8; ++g) {
        const ulonglong2* gp = pc2 + g * 512 + lane;
        unsigned gmin = FULL;
#pragma unroll
        for (int r = 0; r < 4; ++r) {
            const ulonglong2 c0 = __ldg(gp + r * 128);
            const ulonglong2 c1 = __ldg(gp + r * 128 + 32);
            const ulonglong2 c2 = __ldg(gp + r * 128 + 64);
            const ulonglong2 c3 = __ldg(gp + r * 128 + 96);
            const unsigned k0 = (unsigned)__popcll(qc ^ c0.x) * 8192u + e0;
            const unsigned k1 = (unsigned)__popcll(qc ^ c0.y) * 8192u + e1;
            const unsigned k2 = (unsigned)__popcll(qc ^ c1.x) * 8192u + e2;
            const unsigned k3 = (unsigned)__popcll(qc ^ c1.y) * 8192u + e3;
            const unsigned k4 = (unsigned)__popcll(qc ^ c2.x) * 8192u + e4;
            const unsigned k5 = (unsigned)__popcll(qc ^ c2.y) * 8192u + e5;
            const unsigned k6 = (unsigned)__popcll(qc ^ c3.x) * 8192u + e6;
            const unsigned k7 = (unsigned)__popcll(qc ^ c3.y) * 8192u + e7;
            const unsigned m01 = min(k0, k1), m23 = min(k2, k3);
            const unsigned m45 = min(k4, k5), m67 = min(k6, k7);
            const unsigned rmin = min(min(m01, m23), min(m45, m67));
            gmin = min(gmin, rmin + (unsigned)(g * 1024 + r * 256));
        }
        gm[g] = gmin;
        try_insert(gmin);
    }

    // ---------------- Phase 2: exact rescan of candidate groups -------------
#pragma unroll
    for (int g = 0; g < 8; ++g) {
        unsigned mask = __ballot_sync(FULL, gm[g] <= thr);
        while (mask) {
            const int src = __ffs(mask) - 1;
            mask &= mask - 1;
            const unsigned gval = __shfl_sync(FULL, gm[g], src);
            // lane m rescans candidate m of group (src, g)
            const int i   = g * 4 + (lane >> 3);
            const int idx = i * 256 + src * 2 + ((lane >> 1) & 3) * 64 + (lane & 1);
            const unsigned long long c = __ldg(pc + idx);
            unsigned key = (unsigned)__popcll(qc ^ c) * 8192u + (unsigned)idx;
            if (key == gval) key = FULL;   // dedup: group min already in lst
            try_insert(key);
            mask &= __ballot_sync(FULL, gm[g] <= thr);
        }
    }

    if (lane < KK) {
        const unsigned idx  = lst & 0x1FFFu;
        const float    dist = (float)(lst >> 13);
        const size_t basep = (size_t)gwarp * KK + lane;
        out[basep] = (float)idx;
        out[(size_t)BB * NQ * KK + basep] = dist;
    }
}

// ---------------------------------------------------------------------------
extern "C" void kernel_launch(void* const* d_in, const int* in_sizes, int n_in,
                              void* d_out, int out_size)
{
    const float* qpts = (const float*)d_in[0];
    const float* pts  = (const float*)d_in[1];
    const float* proj = (const float*)d_in[2];
    float* out = (float*)d_out;

    unsigned long long* qcode_ptr;
    unsigned long long* pcode_ptr;
    cudaGetSymbolAddress((void**)&qcode_ptr, g_qcode);
    cudaGetSymbolAddress((void**)&pcode_ptr, g_pcode);

    hash_kernel<<<1280, 256>>>(qpts, pts, proj, qcode_ptr, pcode_ptr);
    knn_kernel<<<1024, 256>>>(out);
}

// round 16
// speedup vs baseline: 1.1662x; 1.1662x over previous
#include <cuda_runtime.h>
#include <stdint.h>

#define BB   4
#define NQ   2048
#define NP_  8192
#define DD   256
#define FF   40
#define KK   16
#define FULL 0xFFFFFFFFu

__device__ unsigned long long g_qcode[BB * NQ];
__device__ unsigned long long g_pcode[BB * NP_];

// ---- packed f32x2 helpers (Blackwell) --------------------------------------
__device__ __forceinline__ unsigned long long fmul2(
    unsigned long long a, unsigned long long b) {
    unsigned long long d;
    asm("mul.rn.f32x2 %0, %1, %2;" : "=l"(d) : "l"(a), "l"(b));
    return d;
}
__device__ __forceinline__ unsigned long long ffma2(
    unsigned long long a, unsigned long long b, unsigned long long c) {
    unsigned long long d;
    asm("fma.rn.f32x2 %0, %1, %2, %3;" : "=l"(d) : "l"(a), "l"(b), "l"(c));
    return d;
}
__device__ __forceinline__ float hsum2(unsigned long long v) {
    float lo, hi;
    asm("mov.b64 {%0, %1}, %2;" : "=f"(lo), "=f"(hi) : "l"(v));
    return lo + hi;
}

// ---------------------------------------------------------------------------
// Hash kernel (unchanged from verified R15): one warp per 4 rows; proj smem
// amortized 4x; packed FFMA2 dots; 8-feature multi-reduction + ballot signs.
// ---------------------------------------------------------------------------
__global__ __launch_bounds__(256) void hash_kernel(
    const float* __restrict__ qpts,
    const float* __restrict__ ppts,
    const float* __restrict__ proj,
    unsigned long long* __restrict__ qcodes,
    unsigned long long* __restrict__ pcodes)
{
    __shared__ __align__(16) float sproj[FF * DD];  // 40 KB
    {
        const float4* p4 = reinterpret_cast<const float4*>(proj);
        float4* s4 = reinterpret_cast<float4*>(sproj);
        for (int i = threadIdx.x; i < (FF * DD) / 4; i += blockDim.x)
            s4[i] = p4[i];
    }
    __syncthreads();

    const int warp = threadIdx.x >> 5;
    const int lane = threadIdx.x & 31;
    const int row0 = (blockIdx.x * 8 + warp) * 4;   // 1280*8*4 = 40960 exact

    const int NQT = BB * NQ;
    const float* src;
    unsigned long long* dst;
    int r0;
    if (row0 < NQT) { src = qpts; dst = qcodes; r0 = row0; }
    else            { src = ppts; dst = pcodes; r0 = row0 - NQT; }

    unsigned long long vp[4][4];
#pragma unroll
    for (int r = 0; r < 4; ++r) {
        const ulonglong2* rp = reinterpret_cast<const ulonglong2*>(
            src + (size_t)(r0 + r) * DD);
        ulonglong2 a = __ldg(rp + lane);
        ulonglong2 b = __ldg(rp + lane + 32);
        vp[r][0] = a.x; vp[r][1] = a.y; vp[r][2] = b.x; vp[r][3] = b.y;
    }

    const bool hi16 = (lane & 16) != 0;
    const bool hi8  = (lane & 8)  != 0;
    const bool hi4  = (lane & 4)  != 0;

    unsigned long long code[4] = {0ull, 0ull, 0ull, 0ull};

#pragma unroll
    for (int g = 0; g < 5; ++g) {
        const int brev[8] = {0, 4, 2, 6, 1, 5, 3, 7};
        float t[4][8];
#pragma unroll
        for (int s = 0; s < 8; ++s) {
            const int f = g * 8 + brev[s];
            const ulonglong2* sp = reinterpret_cast<const ulonglong2*>(sproj + f * DD);
            ulonglong2 P0 = sp[lane];
            ulonglong2 P1 = sp[lane + 32];
#pragma unroll
            for (int r = 0; r < 4; ++r) {
                unsigned long long acc = fmul2(vp[r][0], P0.x);
                acc = ffma2(vp[r][1], P0.y, acc);
                acc = ffma2(vp[r][2], P1.x, acc);
                acc = ffma2(vp[r][3], P1.y, acc);
                t[r][s] = hsum2(acc);
            }
        }
#pragma unroll
        for (int r = 0; r < 4; ++r) {
            float rr[4];
#pragma unroll
            for (int p = 0; p < 4; ++p) {
                float c = hi16 ? t[r][2 * p + 1] : t[r][2 * p];
                float d = hi16 ? t[r][2 * p]     : t[r][2 * p + 1];
                rr[p] = c + __shfl_xor_sync(FULL, d, 16);
            }
            float ss[2];
#pragma unroll
            for (int p = 0; p < 2; ++p) {
                float c = hi8 ? rr[2 * p + 1] : rr[2 * p];
                float d = hi8 ? rr[2 * p]     : rr[2 * p + 1];
                ss[p] = c + __shfl_xor_sync(FULL, d, 8);
            }
            float c = hi4 ? ss[1] : ss[0];
            float d = hi4 ? ss[0] : ss[1];
            float u = c + __shfl_xor_sync(FULL, d, 4);
            u += __shfl_xor_sync(FULL, u, 2);
            u += __shfl_xor_sync(FULL, u, 1);

            unsigned bal = __ballot_sync(FULL, u > 0.0f);
            unsigned x = bal & 0x11111111u;
            x = (x | (x >> 3))  & 0x03030303u;
            x = (x | (x >> 6))  & 0x000F000Fu;
            x = (x | (x >> 12)) & 0xFFu;
            code[r] |= (unsigned long long)x << (g * 8);
        }
    }
    if (lane == 0) {
        dst[r0 + 0] = code[0];
        dst[r0 + 1] = code[1];
        dst[r0 + 2] = code[2];
        dst[r0 + 3] = code[3];
    }
}

// ---------------------------------------------------------------------------
// knn kernel v5: one warp per query.
// Phase 1 (branchless): each (lane,g) group of 32 candidates reduced to its
//   minimum key a[g]; keys relative+rebased as in R15 (provably identical to
//   key = dist*8192 + idx). popcll halves folded into two IMADs (fma pipe).
// Selection (branchless): lane-local sort of a[0..7] (19-comparator network),
//   then 16 rounds of __reduce_min_sync + predicated pop -> lst sorted
//   ascending in lanes 0..15, thr = lst[15] = exact 16th-smallest group-min.
// Phase 2 (exact): the 16 seeds come from 16 DISTINCT groups; the key itself
//   encodes its group: idx = key & 8191, g = idx>>10, src = (idx>>1)&31.
//   For each seed (ascending order -> max pruning): if gkey > thr_now the
//   group provably holds no top-16 key (>=16 resident keys are smaller);
//   else rescan its 32 candidates (lane m -> round m>>3, slot m&7), dedup
//   the group min (still resident iff gkey <= thr_now), try_insert the rest.
// ---------------------------------------------------------------------------
__global__ __launch_bounds__(256, 4) void knn_kernel(float* __restrict__ out)
{
    const int gwarp = (blockIdx.x * blockDim.x + threadIdx.x) >> 5;
    const int lane  = threadIdx.x & 31;
    const int b     = gwarp >> 11;

    const unsigned long long qc = g_qcode[gwarp];
    const unsigned long long* __restrict__ pc = g_pcode + (size_t)b * NP_;
    const ulonglong2* __restrict__ pc2 = reinterpret_cast<const ulonglong2*>(pc);

    // Hoisted per-lane relative index addends
    const unsigned L2 = (unsigned)lane * 2u;
    const unsigned e0 = L2,       e1 = L2 + 1;
    const unsigned e2 = L2 + 64,  e3 = L2 + 65;
    const unsigned e4 = L2 + 128, e5 = L2 + 129;
    const unsigned e6 = L2 + 192, e7 = L2 + 193;

    // ---------------- Phase 1: branchless group-min scan ----------------
    unsigned a[8];
#pragma unroll
    for (int g = 0; g < 8; ++g) {
        const ulonglong2* gp = pc2 + g * 512 + lane;
        unsigned gmin = FULL;
#pragma unroll
        for (int r = 0; r < 4; ++r) {
            const ulonglong2 c0 = __ldg(gp + r * 128);
            const ulonglong2 c1 = __ldg(gp + r * 128 + 32);
            const ulonglong2 c2 = __ldg(gp + r * 128 + 64);
            const ulonglong2 c3 = __ldg(gp + r * 128 + 96);
            const unsigned long long x0 = qc ^ c0.x, x1 = qc ^ c0.y;
            const unsigned long long x2 = qc ^ c1.x, x3 = qc ^ c1.y;
            const unsigned long long x4 = qc ^ c2.x, x5 = qc ^ c2.y;
            const unsigned long long x6 = qc ^ c3.x, x7 = qc ^ c3.y;
            // popcll halves folded into two IMADs (fma pipe), no IADD3 on alu
            const unsigned k0 = __popc((unsigned)x0) * 8192u + (__popc((unsigned)(x0 >> 32)) * 8192u + e0);
            const unsigned k1 = __popc((unsigned)x1) * 8192u + (__popc((unsigned)(x1 >> 32)) * 8192u + e1);
            const unsigned k2 = __popc((unsigned)x2) * 8192u + (__popc((unsigned)(x2 >> 32)) * 8192u + e2);
            const unsigned k3 = __popc((unsigned)x3) * 8192u + (__popc((unsigned)(x3 >> 32)) * 8192u + e3);
            const unsigned k4 = __popc((unsigned)x4) * 8192u + (__popc((unsigned)(x4 >> 32)) * 8192u + e4);
            const unsigned k5 = __popc((unsigned)x5) * 8192u + (__popc((unsigned)(x5 >> 32)) * 8192u + e5);
            const unsigned k6 = __popc((unsigned)x6) * 8192u + (__popc((unsigned)(x6 >> 32)) * 8192u + e6);
            const unsigned k7 = __popc((unsigned)x7) * 8192u + (__popc((unsigned)(x7 >> 32)) * 8192u + e7);
            const unsigned m01 = min(k0, k1), m23 = min(k2, k3);
            const unsigned m45 = min(k4, k5), m67 = min(k6, k7);
            const unsigned rmin = min(min(m01, m23), min(m45, m67));
            gmin = min(gmin, rmin + (unsigned)(g * 1024 + r * 256));
        }
        a[g] = gmin;
    }

    // ---------------- Selection: sort-8 network + 16x redux-min pop ---------
    {
        auto cas = [&](int i, int j) {
            unsigned lo = min(a[i], a[j]);
            unsigned hi = a[i] > a[j] ? a[i] : a[j];
            a[i] = lo; a[j] = hi;
        };
        cas(0,1); cas(2,3); cas(4,5); cas(6,7);
        cas(0,2); cas(1,3); cas(4,6); cas(5,7);
        cas(1,2); cas(5,6);
        cas(0,4); cas(1,5); cas(2,6); cas(3,7);
        cas(2,4); cas(3,5);
        cas(1,2); cas(3,4); cas(5,6);
    }
    unsigned res = FULL;
#pragma unroll
    for (int r = 0; r < KK; ++r) {
        const unsigned m = __reduce_min_sync(FULL, a[0]);
        const bool own = (a[0] == m);   // unique keys -> exactly one owner
#pragma unroll
        for (int j = 0; j < 7; ++j) a[j] = own ? a[j + 1] : a[j];
        a[7] = own ? FULL : a[7];
        if (lane == r) res = m;
    }
    unsigned lst = res;                              // sorted; lanes>=16 FULL
    unsigned thr = __shfl_sync(FULL, res, KK - 1);
    const unsigned seed = lst;                       // snapshot of 16 seeds

    auto try_insert = [&](unsigned key) {
        unsigned mask = __ballot_sync(FULL, key < thr);
        while (mask) {
            const int src = __ffs(mask) - 1;
            mask &= mask - 1;
            const unsigned kb  = __shfl_sync(FULL, key, src);
            const unsigned blt = __ballot_sync(FULL, lst < kb);
            const int pos = __popc(blt);
            if (pos < KK) {
                const unsigned up = __shfl_up_sync(FULL, lst, 1);
                if (lane < KK) {
                    if (lane > pos)       lst = up;
                    else if (lane == pos) lst = kb;
                }
                thr = __shfl_sync(FULL, lst, KK - 1);
                mask &= __ballot_sync(FULL, key < thr);
            }
        }
    };

    // ---------------- Phase 2: exact rescan of the 16 seed groups -----------
    // lane m covers candidate m of the group: round m>>3, slot m&7.
    const unsigned lanepart = ((unsigned)(lane >> 3)) * 256u
                            + (((unsigned)lane >> 1) & 3u) * 64u
                            + ((unsigned)lane & 1u);
#pragma unroll 1
    for (int r = 0; r < KK; ++r) {
        const unsigned gkey = __shfl_sync(FULL, seed, r);   // warp-uniform
        if (gkey > thr) continue;   // uniform branch; group holds no top-16 key
        const unsigned gi   = gkey & 8191u;
        const unsigned gbase = (gi & ~1023u) + ((gi & 63u) & ~1u); // g*1024 + src*2
        const int idx = (int)(gbase + lanepart);
        const unsigned long long x = qc ^ __ldg(pc + idx);
        unsigned key = __popc((unsigned)x) * 8192u
                     + (__popc((unsigned)(x >> 32)) * 8192u + (unsigned)idx);
        if (key == gkey) key = FULL;   // dedup: group min already resident
        try_insert(key);
    }

    if (lane < KK) {
        const unsigned idx  = lst & 0x1FFFu;
        const float    dist = (float)(lst >> 13);
        const size_t basep = (size_t)gwarp * KK + lane;
        out[basep] = (float)idx;
        out[(size_t)BB * NQ * KK + basep] = dist;
    }
}

// ---------------------------------------------------------------------------
extern "C" void kernel_launch(void* const* d_in, const int* in_sizes, int n_in,
                              void* d_out, int out_size)
{
    const float* qpts = (const float*)d_in[0];
    const float* pts  = (const float*)d_in[1];
    const float* proj = (const float*)d_in[2];
    float* out = (float*)d_out;

    unsigned long long* qcode_ptr;
    unsigned long long* pcode_ptr;
    cudaGetSymbolAddress((void**)&qcode_ptr, g_qcode);
    cudaGetSymbolAddress((void**)&pcode_ptr, g_pcode);

    hash_kernel<<<1280, 256>>>(qpts, pts, proj, qcode_ptr, pcode_ptr);
    knn_kernel<<<1024, 256>>>(out);
}